// round 2
// baseline (speedup 1.0000x reference)
#include <cuda_runtime.h>
#include <math.h>

// Problem shapes (fixed by dataset)
#define SS 2048
#define BB 32
#define HH 1024

// K_A tiling: split the o (output/contraction) dimension into NOB chunks of OC
#define OC  64
#define NOB (HH / OC)   // 16

// Scratch (static __device__ — no allocations allowed)
__device__ float g_u_part[NOB][BB * HH];  // 2 MB
__device__ float g_u[BB * HH];            // 128 KB
__device__ float g_scores[BB * SS];       // 256 KB

// ---------------------------------------------------------------------------
// K_A: u_part[ob][b][h] = sum_{o in chunk ob} hidden[b,o] * W[o,h]
// grid (HH/128, NOB), block 128. W element read exactly once across the grid.
// ---------------------------------------------------------------------------
__global__ void __launch_bounds__(128) k_upart(const float* __restrict__ hidden,
                                               const float* __restrict__ W) {
    __shared__ float hs[OC * BB];  // hs[o*BB + b] = hidden[b, o0+o]
    const int h0 = blockIdx.x * 128;
    const int o0 = blockIdx.y * OC;

    for (int i = threadIdx.x; i < OC * BB; i += 128) {
        int o = i >> 5;       // /32
        int b = i & 31;
        hs[i] = hidden[b * HH + o0 + o];
    }
    __syncthreads();

    const int h = h0 + threadIdx.x;
    float acc[BB];
#pragma unroll
    for (int b = 0; b < BB; ++b) acc[b] = 0.f;

    for (int o = 0; o < OC; ++o) {
        float w = W[(size_t)(o0 + o) * HH + h];
#pragma unroll
        for (int b = 0; b < BB; ++b) acc[b] = fmaf(hs[o * BB + b], w, acc[b]);
    }

#pragma unroll
    for (int b = 0; b < BB; ++b) g_u_part[blockIdx.y][b * HH + h] = acc[b];
}

// ---------------------------------------------------------------------------
// K_B: u[i] = sum over the NOB partials. grid 128, block 256.
// ---------------------------------------------------------------------------
__global__ void __launch_bounds__(256) k_ureduce() {
    int i = blockIdx.x * 256 + threadIdx.x;  // i < BB*HH = 32768
    float s = 0.f;
#pragma unroll
    for (int p = 0; p < NOB; ++p) s += g_u_part[p][i];
    g_u[i] = s;
}

// ---------------------------------------------------------------------------
// K_C (dominant, HBM-bound): scores[b,s] = u[b] . enc[s,b,:]
// grid (SS/32, BB), block 256 (8 warps). Each warp handles 4 consecutive s.
// u[b] cached in smem (4 KB). enc rows are contiguous 4 KB -> float4 coalesced.
// ---------------------------------------------------------------------------
#define SPW 4  // s-rows per warp

__global__ void __launch_bounds__(256) k_scores(const float* __restrict__ enc,
                                                float* __restrict__ scores) {
    const int b = blockIdx.y;
    __shared__ float4 u_sm[HH / 4];  // 256 float4

    const float4* ub = reinterpret_cast<const float4*>(g_u + b * HH);
    for (int i = threadIdx.x; i < HH / 4; i += 256) u_sm[i] = ub[i];
    __syncthreads();

    const int warp = threadIdx.x >> 5;
    const int lane = threadIdx.x & 31;
    const int s_base = (blockIdx.x * 8 + warp) * SPW;

#pragma unroll
    for (int r = 0; r < SPW; ++r) {
        const int s = s_base + r;
        const float4* row =
            reinterpret_cast<const float4*>(enc + ((size_t)s * BB + b) * HH);
        float acc = 0.f;
#pragma unroll
        for (int c = 0; c < 8; ++c) {
            float4 e = row[c * 32 + lane];
            float4 u = u_sm[c * 32 + lane];
            acc += e.x * u.x + e.y * u.y + e.z * u.z + e.w * u.w;
        }
#pragma unroll
        for (int off = 16; off; off >>= 1)
            acc += __shfl_xor_sync(0xFFFFFFFFu, acc, off);
        if (lane == 0) scores[b * SS + s] = acc;
    }
}

// ---------------------------------------------------------------------------
// K_D: per-b softmax over s (row length 2048). grid BB, block 256.
// Writes d_out directly ([B,1,S] is contiguous [B*S]).
// ---------------------------------------------------------------------------
__global__ void __launch_bounds__(256) k_softmax(float* __restrict__ out) {
    const int b = blockIdx.x;
    const int t = threadIdx.x;
    __shared__ float red[8];

    float v[8];
    float m = -1e30f;
#pragma unroll
    for (int i = 0; i < 8; ++i) {
        v[i] = g_scores[b * SS + t + i * 256];
        m = fmaxf(m, v[i]);
    }
#pragma unroll
    for (int off = 16; off; off >>= 1)
        m = fmaxf(m, __shfl_xor_sync(0xFFFFFFFFu, m, off));
    if ((t & 31) == 0) red[t >> 5] = m;
    __syncthreads();
    float bm = red[0];
#pragma unroll
    for (int w = 1; w < 8; ++w) bm = fmaxf(bm, red[w]);
    __syncthreads();  // before reusing red[]

    float sum = 0.f;
#pragma unroll
    for (int i = 0; i < 8; ++i) {
        v[i] = expf(v[i] - bm);
        sum += v[i];
    }
#pragma unroll
    for (int off = 16; off; off >>= 1)
        sum += __shfl_xor_sync(0xFFFFFFFFu, sum, off);
    if ((t & 31) == 0) red[t >> 5] = sum;
    __syncthreads();
    float tot = red[0];
#pragma unroll
    for (int w = 1; w < 8; ++w) tot += red[w];

    float inv = 1.f / tot;
#pragma unroll
    for (int i = 0; i < 8; ++i) out[b * SS + t + i * 256] = v[i] * inv;
}

// ---------------------------------------------------------------------------
// Inputs (metadata order): hidden [B,H], encoder_outputs [S,B,H], W [H,H], b [H]
// The bias input is mathematically irrelevant (softmax shift invariance).
// ---------------------------------------------------------------------------
extern "C" void kernel_launch(void* const* d_in, const int* in_sizes, int n_in,
                              void* d_out, int out_size) {
    const float* hidden = (const float*)d_in[0];
    const float* enc    = (const float*)d_in[1];
    const float* W      = (const float*)d_in[2];
    float* out          = (float*)d_out;

    k_upart<<<dim3(HH / 128, NOB), 128>>>(hidden, W);
    k_ureduce<<<(BB * HH) / 256, 256>>>();

    float* scores_ptr;
    cudaGetSymbolAddress((void**)&scores_ptr, g_scores);
    k_scores<<<dim3(SS / (8 * SPW), BB), 256>>>(enc, scores_ptr);
    k_softmax<<<BB, 256>>>(out);
}

// round 3
// speedup vs baseline: 1.0004x; 1.0004x over previous
#include <cuda_runtime.h>
#include <math.h>

// Problem shapes (fixed by dataset)
#define SS 2048
#define BB 32
#define HH 1024

// K_A tiling: split the o (output/contraction) dimension into NOB chunks of OC
#define OC  64
#define NOB (HH / OC)   // 16

// Scratch (static __device__ — no allocations allowed)
__device__ float g_u_part[NOB][BB * HH];  // 2 MB
__device__ float g_u[BB * HH];            // 128 KB
__device__ float g_scores[BB * SS];       // 256 KB

// ---------------------------------------------------------------------------
// K_A: u_part[ob][b][h] = sum_{o in chunk ob} hidden[b,o] * W[o,h]
// grid (HH/128, NOB), block 128. W element read exactly once across the grid.
// ---------------------------------------------------------------------------
__global__ void __launch_bounds__(128) k_upart(const float* __restrict__ hidden,
                                               const float* __restrict__ W) {
    __shared__ float hs[OC * BB];  // hs[o*BB + b] = hidden[b, o0+o]
    const int h0 = blockIdx.x * 128;
    const int o0 = blockIdx.y * OC;

    for (int i = threadIdx.x; i < OC * BB; i += 128) {
        int o = i >> 5;       // /32
        int b = i & 31;
        hs[i] = hidden[b * HH + o0 + o];
    }
    __syncthreads();

    const int h = h0 + threadIdx.x;
    float acc[BB];
#pragma unroll
    for (int b = 0; b < BB; ++b) acc[b] = 0.f;

    for (int o = 0; o < OC; ++o) {
        float w = W[(size_t)(o0 + o) * HH + h];
#pragma unroll
        for (int b = 0; b < BB; ++b) acc[b] = fmaf(hs[o * BB + b], w, acc[b]);
    }

#pragma unroll
    for (int b = 0; b < BB; ++b) g_u_part[blockIdx.y][b * HH + h] = acc[b];
}

// ---------------------------------------------------------------------------
// K_B: u[i] = sum over the NOB partials. grid 128, block 256.
// ---------------------------------------------------------------------------
__global__ void __launch_bounds__(256) k_ureduce() {
    int i = blockIdx.x * 256 + threadIdx.x;  // i < BB*HH = 32768
    float s = 0.f;
#pragma unroll
    for (int p = 0; p < NOB; ++p) s += g_u_part[p][i];
    g_u[i] = s;
}

// ---------------------------------------------------------------------------
// K_C (dominant, HBM-bound): scores[b,s] = u[b] . enc[s,b,:]
// grid (SS/32, BB), block 256 (8 warps). Each warp handles 4 consecutive s.
// u[b] cached in smem (4 KB). enc rows are contiguous 4 KB -> float4 coalesced.
// ---------------------------------------------------------------------------
#define SPW 4  // s-rows per warp

__global__ void __launch_bounds__(256) k_scores(const float* __restrict__ enc,
                                                float* __restrict__ scores) {
    const int b = blockIdx.y;
    __shared__ float4 u_sm[HH / 4];  // 256 float4

    const float4* ub = reinterpret_cast<const float4*>(g_u + b * HH);
    for (int i = threadIdx.x; i < HH / 4; i += 256) u_sm[i] = ub[i];
    __syncthreads();

    const int warp = threadIdx.x >> 5;
    const int lane = threadIdx.x & 31;
    const int s_base = (blockIdx.x * 8 + warp) * SPW;

#pragma unroll
    for (int r = 0; r < SPW; ++r) {
        const int s = s_base + r;
        const float4* row =
            reinterpret_cast<const float4*>(enc + ((size_t)s * BB + b) * HH);
        float acc = 0.f;
#pragma unroll
        for (int c = 0; c < 8; ++c) {
            float4 e = row[c * 32 + lane];
            float4 u = u_sm[c * 32 + lane];
            acc += e.x * u.x + e.y * u.y + e.z * u.z + e.w * u.w;
        }
#pragma unroll
        for (int off = 16; off; off >>= 1)
            acc += __shfl_xor_sync(0xFFFFFFFFu, acc, off);
        if (lane == 0) scores[b * SS + s] = acc;
    }
}

// ---------------------------------------------------------------------------
// K_D: per-b softmax over s (row length 2048). grid BB, block 256.
// Writes d_out directly ([B,1,S] is contiguous [B*S]).
// ---------------------------------------------------------------------------
__global__ void __launch_bounds__(256) k_softmax(float* __restrict__ out) {
    const int b = blockIdx.x;
    const int t = threadIdx.x;
    __shared__ float red[8];

    float v[8];
    float m = -1e30f;
#pragma unroll
    for (int i = 0; i < 8; ++i) {
        v[i] = g_scores[b * SS + t + i * 256];
        m = fmaxf(m, v[i]);
    }
#pragma unroll
    for (int off = 16; off; off >>= 1)
        m = fmaxf(m, __shfl_xor_sync(0xFFFFFFFFu, m, off));
    if ((t & 31) == 0) red[t >> 5] = m;
    __syncthreads();
    float bm = red[0];
#pragma unroll
    for (int w = 1; w < 8; ++w) bm = fmaxf(bm, red[w]);
    __syncthreads();  // before reusing red[]

    float sum = 0.f;
#pragma unroll
    for (int i = 0; i < 8; ++i) {
        v[i] = expf(v[i] - bm);
        sum += v[i];
    }
#pragma unroll
    for (int off = 16; off; off >>= 1)
        sum += __shfl_xor_sync(0xFFFFFFFFu, sum, off);
    if ((t & 31) == 0) red[t >> 5] = sum;
    __syncthreads();
    float tot = red[0];
#pragma unroll
    for (int w = 1; w < 8; ++w) tot += red[w];

    float inv = 1.f / tot;
#pragma unroll
    for (int i = 0; i < 8; ++i) out[b * SS + t + i * 256] = v[i] * inv;
}

// ---------------------------------------------------------------------------
// Inputs (metadata order): hidden [B,H], encoder_outputs [S,B,H], W [H,H], b [H]
// The bias input is mathematically irrelevant (softmax shift invariance).
// ---------------------------------------------------------------------------
extern "C" void kernel_launch(void* const* d_in, const int* in_sizes, int n_in,
                              void* d_out, int out_size) {
    const float* hidden = (const float*)d_in[0];
    const float* enc    = (const float*)d_in[1];
    const float* W      = (const float*)d_in[2];
    float* out          = (float*)d_out;

    k_upart<<<dim3(HH / 128, NOB), 128>>>(hidden, W);
    k_ureduce<<<(BB * HH) / 256, 256>>>();

    float* scores_ptr;
    cudaGetSymbolAddress((void**)&scores_ptr, g_scores);
    k_scores<<<dim3(SS / (8 * SPW), BB), 256>>>(enc, scores_ptr);
    k_softmax<<<BB, 256>>>(out);
}

// round 4
// speedup vs baseline: 1.4386x; 1.4380x over previous
#include <cuda_runtime.h>
#include <math.h>

// Problem shapes (fixed by dataset)
#define SS 2048
#define BB 32
#define HH 1024

// K_A tiling: split the o (contraction) dimension into NOB chunks of OC
#define OC  32
#define NOB (HH / OC)   // 32

// Scratch (static __device__ — no allocations allowed)
__device__ float g_u_part[NOB][BB * HH];  // 4 MB
__device__ float g_u[BB * HH];            // 128 KB
__device__ float g_scores[BB * SS];       // 256 KB

// ---------------------------------------------------------------------------
// K_A: u_part[ob][b][h] = sum_{o in chunk ob} hidden[b,o] * W[o,h]
// grid (HH/128, NOB) = (8, 32) = 256 blocks, block 128. W read exactly once.
// ---------------------------------------------------------------------------
__global__ void __launch_bounds__(128) k_upart(const float* __restrict__ hidden,
                                               const float* __restrict__ W) {
    __shared__ float hs[OC * BB];  // hs[o*BB + b] = hidden[b, o0+o]
    const int h0 = blockIdx.x * 128;
    const int o0 = blockIdx.y * OC;

    for (int i = threadIdx.x; i < OC * BB; i += 128) {
        int o = i >> 5;       // /32
        int b = i & 31;
        hs[i] = hidden[b * HH + o0 + o];
    }
    __syncthreads();

    const int h = h0 + threadIdx.x;
    float acc[BB];
#pragma unroll
    for (int b = 0; b < BB; ++b) acc[b] = 0.f;

    for (int o = 0; o < OC; ++o) {
        float w = W[(size_t)(o0 + o) * HH + h];
#pragma unroll
        for (int b = 0; b < BB; ++b) acc[b] = fmaf(hs[o * BB + b], w, acc[b]);
    }

#pragma unroll
    for (int b = 0; b < BB; ++b) g_u_part[blockIdx.y][b * HH + h] = acc[b];
}

// ---------------------------------------------------------------------------
// K_B: u[i] = sum over the NOB partials. grid 128, block 256.
// ---------------------------------------------------------------------------
__global__ void __launch_bounds__(256) k_ureduce() {
    int i = blockIdx.x * 256 + threadIdx.x;  // i < BB*HH = 32768
    float s = 0.f;
#pragma unroll
    for (int p = 0; p < NOB; ++p) s += g_u_part[p][i];
    g_u[i] = s;
}

// ---------------------------------------------------------------------------
// K_C (dominant, HBM-bound): scores[b,s] = u[b] . enc[s,b,:]
// Block = one PAIR of s rows (grid SS/2 = 1024), 1024 threads = 32 warps,
// warp w handles b = w. Each block streams 2 x 128 KB fully-contiguous spans
// of enc. u[b] lives in 8 float4 registers per warp, fetched via __ldg
// (L1-cached; enc uses __ldcs evict-first so it doesn't evict u).
// ---------------------------------------------------------------------------
__global__ void __launch_bounds__(1024) k_scores(const float* __restrict__ enc,
                                                 float* __restrict__ scores) {
    const int warp = threadIdx.x >> 5;
    const int lane = threadIdx.x & 31;
    const int b = warp;               // 32 warps == 32 batches
    const int s0 = blockIdx.x * 2;

    const float4* ub = reinterpret_cast<const float4*>(g_u + b * HH);
    float4 u[8];
#pragma unroll
    for (int c = 0; c < 8; ++c) u[c] = __ldg(&ub[c * 32 + lane]);

    const float4* r0 =
        reinterpret_cast<const float4*>(enc + ((size_t)s0 * BB + b) * HH);
    const float4* r1 =
        reinterpret_cast<const float4*>(enc + ((size_t)(s0 + 1) * BB + b) * HH);

    float a0 = 0.f, a1 = 0.f;
#pragma unroll
    for (int c = 0; c < 8; ++c) {
        float4 e0 = __ldcs(&r0[c * 32 + lane]);
        float4 e1 = __ldcs(&r1[c * 32 + lane]);
        a0 += e0.x * u[c].x + e0.y * u[c].y + e0.z * u[c].z + e0.w * u[c].w;
        a1 += e1.x * u[c].x + e1.y * u[c].y + e1.z * u[c].z + e1.w * u[c].w;
    }

#pragma unroll
    for (int off = 16; off; off >>= 1) {
        a0 += __shfl_xor_sync(0xFFFFFFFFu, a0, off);
        a1 += __shfl_xor_sync(0xFFFFFFFFu, a1, off);
    }
    if (lane == 0) {
        scores[b * SS + s0]     = a0;
        scores[b * SS + s0 + 1] = a1;
    }
}

// ---------------------------------------------------------------------------
// K_D: per-b softmax over s (row length 2048). grid BB, block 1024.
// Writes d_out directly ([B,1,S] is contiguous [B*S]).
// ---------------------------------------------------------------------------
__global__ void __launch_bounds__(1024) k_softmax(float* __restrict__ out) {
    const int b = blockIdx.x;
    const int t = threadIdx.x;
    const int warp = t >> 5;
    const int lane = t & 31;
    __shared__ float red[32];

    float v0 = g_scores[b * SS + t];
    float v1 = g_scores[b * SS + t + 1024];

    // --- max ---
    float m = fmaxf(v0, v1);
#pragma unroll
    for (int off = 16; off; off >>= 1)
        m = fmaxf(m, __shfl_xor_sync(0xFFFFFFFFu, m, off));
    if (lane == 0) red[warp] = m;
    __syncthreads();
    if (warp == 0) {
        float x = red[lane];
#pragma unroll
        for (int off = 16; off; off >>= 1)
            x = fmaxf(x, __shfl_xor_sync(0xFFFFFFFFu, x, off));
        if (lane == 0) red[0] = x;
    }
    __syncthreads();
    const float bm = red[0];
    __syncthreads();  // before reusing red[]

    // --- exp + sum ---
    v0 = __expf(v0 - bm);
    v1 = __expf(v1 - bm);
    float s = v0 + v1;
#pragma unroll
    for (int off = 16; off; off >>= 1)
        s += __shfl_xor_sync(0xFFFFFFFFu, s, off);
    if (lane == 0) red[warp] = s;
    __syncthreads();
    if (warp == 0) {
        float x = red[lane];
#pragma unroll
        for (int off = 16; off; off >>= 1)
            x += __shfl_xor_sync(0xFFFFFFFFu, x, off);
        if (lane == 0) red[0] = x;
    }
    __syncthreads();
    const float inv = 1.f / red[0];

    out[b * SS + t]        = v0 * inv;
    out[b * SS + t + 1024] = v1 * inv;
}

// ---------------------------------------------------------------------------
// Inputs (metadata order): hidden [B,H], encoder_outputs [S,B,H], W [H,H], b [H]
// The bias input is mathematically irrelevant (softmax shift invariance).
// ---------------------------------------------------------------------------
extern "C" void kernel_launch(void* const* d_in, const int* in_sizes, int n_in,
                              void* d_out, int out_size) {
    const float* hidden = (const float*)d_in[0];
    const float* enc    = (const float*)d_in[1];
    const float* W      = (const float*)d_in[2];
    float* out          = (float*)d_out;

    k_upart<<<dim3(HH / 128, NOB), 128>>>(hidden, W);
    k_ureduce<<<(BB * HH) / 256, 256>>>();

    float* scores_ptr;
    cudaGetSymbolAddress((void**)&scores_ptr, g_scores);
    k_scores<<<SS / 2, 1024>>>(enc, scores_ptr);
    k_softmax<<<BB, 1024>>>(out);
}